// round 7
// baseline (speedup 1.0000x reference)
#include <cuda_runtime.h>

#define NQ    12
#define DIM   4096
#define NL    4
#define NT    512
#define KPT   8
// GF(2)-designed swizzle: XOR bit4->b0, bit5->b1, bit6->(b2,b3)
#define SW(i) ((i) ^ (((i) >> 4) & 3) ^ ((((i) >> 6) & 1) * 12))

struct cplx { float x, y; };

__device__ __forceinline__ cplx cmul(cplx a, cplx b) {
    return { a.x*b.x - a.y*b.y, a.x*b.y + a.y*b.x };
}
__device__ __forceinline__ cplx cadd(cplx a, cplx b) {
    return { a.x + b.x, a.y + b.y };
}
__device__ __forceinline__ void mmul(const cplx* A, const cplx* B, cplx* C) {
    C[0] = cadd(cmul(A[0], B[0]), cmul(A[1], B[2]));
    C[1] = cadd(cmul(A[0], B[1]), cmul(A[1], B[3]));
    C[2] = cadd(cmul(A[2], B[0]), cmul(A[3], B[2]));
    C[3] = cadd(cmul(A[2], B[1]), cmul(A[3], B[3]));
}

// real RY rotation on local register bit m of v[8]
__device__ __forceinline__ void apply_ry(float2 v[KPT], float c, float s, int m) {
    #pragma unroll
    for (int h = 0; h < 4; h++) {
        const int k0 = ((h >> m) << (m + 1)) | (h & ((1 << m) - 1));
        const int k1 = k0 | (1 << m);
        const float2 s0 = v[k0];
        const float2 s1 = v[k1];
        v[k0].x = c*s0.x - s*s1.x;
        v[k0].y = c*s0.y - s*s1.y;
        v[k1].x = s*s0.x + c*s1.x;
        v[k1].y = s*s0.y + c*s1.y;
    }
}

__global__ __launch_bounds__(NT, 2)
void qsim_kernel(const float* __restrict__ x,
                 const float* __restrict__ params,
                 float* __restrict__ out)
{
    __shared__ float2 st[DIM];                 // 32 KB state (swizzled)
    __shared__ float2 Dg[NL][4][8];            // fused gamma-diagonals per 3q pass
    __shared__ float2 Da[NL][4][8];            // fused alpha-diagonals per 3q pass
    __shared__ float2 RYcs[NL][NQ];            // (cos, sin) of RY theta/2
    __shared__ float2 EG[NL][NQ], EA[NL][NQ];  // per-qubit half-angle phases
    __shared__ float2 Uc0[9][2];               // fused-U column 0, layer0 qubits 0..8
    __shared__ float  red[NT / 32];

    const int t = threadIdx.x;                 // 0..511
    const int b = blockIdx.x;

    // ---- phase 1: 48 fused gates + ZYZ decomposition ----
    if (t < NL * NQ) {
        const int l = t / NQ;
        const int q = t % NQ;
        const float xv = x[b];
        const float x1 = asinf(xv);
        const float x2 = acosf(xv * xv);

        float c, s;
        sincosf(0.5f * x1, &s, &c);
        cplx RY[4]  = { {c,0.f}, {-s,0.f}, {s,0.f}, {c,0.f} };
        sincosf(0.5f * x2, &s, &c);
        cplx RZ[4]  = { {c,-s}, {0.f,0.f}, {0.f,0.f}, {c,s} };

        const float t0 = params[q * (NL * 3) + l * 3 + 0];
        const float t1 = params[q * (NL * 3) + l * 3 + 1];
        const float t2 = params[q * (NL * 3) + l * 3 + 2];

        sincosf(0.5f * t0, &s, &c);
        cplx RX0[4] = { {c,0.f}, {0.f,-s}, {0.f,-s}, {c,0.f} };
        sincosf(0.5f * t1, &s, &c);
        cplx RZ1[4] = { {c,-s}, {0.f,0.f}, {0.f,0.f}, {c,s} };
        sincosf(0.5f * t2, &s, &c);
        cplx RX2[4] = { {c,0.f}, {0.f,-s}, {0.f,-s}, {c,0.f} };

        cplx A[4], B[4];
        mmul(RZ,  RY, A);
        mmul(RX0, A,  B);
        mmul(RZ1, B,  A);
        mmul(RX2, A,  B);   // fused U in SU(2)

        if (l == 0 && q < 9) {
            Uc0[q][0] = make_float2(B[0].x, B[0].y);   // u00
            Uc0[q][1] = make_float2(B[2].x, B[2].y);   // u10
        }
        // ZYZ: U = RZ(alpha) RY(theta) RZ(gamma)
        const float cc = sqrtf(B[0].x*B[0].x + B[0].y*B[0].y);
        const float ss = sqrtf(B[2].x*B[2].x + B[2].y*B[2].y);
        RYcs[l][q] = make_float2(cc, ss);
        const float aa = atan2f(-B[0].y, B[0].x);   // (alpha+gamma)/2
        const float bb = atan2f( B[2].y, B[2].x);   // (alpha-gamma)/2
        float sg, cg, sa, ca;
        sincosf(0.5f * (aa - bb), &sg, &cg);
        sincosf(0.5f * (aa + bb), &sa, &ca);
        EG[l][q] = make_float2(cg, -sg);
        EA[l][q] = make_float2(ca, -sa);
    }
    __syncthreads();

    // ---- phase 2: 8-entry fused diagonal tables per (layer, pass) ----
    if (t < NL * 4 * 8) {
        const int l = t / 32;
        const int r = t % 32;
        const int p = r / 8;
        const int k = r % 8;
        cplx g = {1.f, 0.f}, a2 = {1.f, 0.f};
        #pragma unroll
        for (int m = 0; m < 3; m++) {
            const int q = 3 * p + 2 - m;            // bit m of k <-> qubit q
            float2 e = EG[l][q];
            if ((k >> m) & 1) e.y = -e.y;
            g = cmul(g, cplx{e.x, e.y});
            e = EA[l][q];
            if ((k >> m) & 1) e.y = -e.y;
            a2 = cmul(a2, cplx{e.x, e.y});
        }
        Dg[l][p][k] = make_float2(g.x, g.y);
        Da[l][p][k] = make_float2(a2.x, a2.y);
    }
    __syncthreads();

    float2 v[KPT];

    #define PASS_BODY(L, P)                                                   \
        {                                                                     \
            _Pragma("unroll")                                                 \
            for (int k = 0; k < KPT; k++) {                                   \
                const float2 d = Dg[L][P][k];                                 \
                const float2 s0 = v[k];                                       \
                v[k].x = d.x*s0.x - d.y*s0.y;                                 \
                v[k].y = d.x*s0.y + d.y*s0.x;                                 \
            }                                                                 \
            _Pragma("unroll")                                                 \
            for (int m = 0; m < 3; m++) {                                     \
                const float2 cs = RYcs[L][3*(P) + 2 - m];                     \
                apply_ry(v, cs.x, cs.y, m);                                   \
            }                                                                 \
            _Pragma("unroll")                                                 \
            for (int k = 0; k < KPT; k++) {                                   \
                const float2 d = Da[L][P][k];                                 \
                const float2 s0 = v[k];                                       \
                v[k].x = d.x*s0.x - d.y*s0.y;                                 \
                v[k].y = d.x*s0.y + d.y*s0.x;                                 \
            }                                                                 \
        }

    // ======== layer 0: qubits 0..8 collapse; pass D is a closed-form column ====
    {
        cplx w = {1.f, 0.f};
        #pragma unroll
        for (int q = 0; q < 9; q++) {
            const float2 e = ((t >> (8 - q)) & 1) ? Uc0[q][1] : Uc0[q][0];
            w = cmul(w, cplx{e.x, e.y});
        }
        const float2 dg0 = Dg[0][3][0];
        const cplx wc = cmul(w, cplx{dg0.x, dg0.y});
        // RY column entries for qubits 9..11 (q = 11 - m for bit m)
        const float2 cs0 = RYcs[0][11];   // bit 0
        const float2 cs1 = RYcs[0][10];   // bit 1
        const float2 cs2 = RYcs[0][9];    // bit 2
        #pragma unroll
        for (int k = 0; k < KPT; k++) {
            const float col = ((k & 1) ? cs0.y : cs0.x) *
                              ((k & 2) ? cs1.y : cs1.x) *
                              ((k & 4) ? cs2.y : cs2.x);
            const float2 d = Da[0][3][k];
            const cplx wcc = { wc.x * col, wc.y * col };
            v[k].x = d.x*wcc.x - d.y*wcc.y;
            v[k].y = d.x*wcc.y + d.y*wcc.x;
        }
        const int base = t << 3;
        #pragma unroll
        for (int k = 0; k < KPT; k++) st[SW(base | k)] = v[k];
        __syncthreads();
    }

    // ======== layers 1..3 ========
    for (int l = 1; l < NL; l++) {
        // pass A (bits 11..9, qubits 0..2), folding CNOT chain i^(i>>1)
        #pragma unroll
        for (int k = 0; k < KPT; k++) {
            const int i = (k << 9) | t;
            const int j = i ^ (i >> 1);
            v[k] = st[SW(j)];
        }
        __syncthreads();
        PASS_BODY(l, 0)
        #pragma unroll
        for (int k = 0; k < KPT; k++) st[SW((k << 9) | t)] = v[k];
        __syncthreads();

        // pass B (bits 8..6, qubits 3..5)
        {
            const int base = ((t >> 6) << 9) | (t & 63);
            #pragma unroll
            for (int k = 0; k < KPT; k++) v[k] = st[SW(base | (k << 6))];
            PASS_BODY(l, 1)
            #pragma unroll
            for (int k = 0; k < KPT; k++) st[SW(base | (k << 6))] = v[k];
            __syncthreads();
        }

        // pass C (bits 5..3, qubits 6..8)
        {
            const int base = ((t >> 3) << 6) | (t & 7);
            #pragma unroll
            for (int k = 0; k < KPT; k++) v[k] = st[SW(base | (k << 3))];
            PASS_BODY(l, 2)
            #pragma unroll
            for (int k = 0; k < KPT; k++) st[SW(base | (k << 3))] = v[k];
            __syncthreads();
        }

        // pass D (bits 2..0, qubits 9..11)
        {
            const int base = t << 3;
            #pragma unroll
            for (int k = 0; k < KPT; k++) v[k] = st[SW(base | k)];
            PASS_BODY(l, 3)
            if (l < NL - 1) {
                #pragma unroll
                for (int k = 0; k < KPT; k++) st[SW(base | k)] = v[k];
                __syncthreads();
            }
            // last layer: stay in registers; CNOT perm preserves bit 11.
        }
    }

    // ---- <Z_0>: sign = bit 11 of i = (t<<3)|k -> bit 8 of t ----
    float acc = 0.f;
    #pragma unroll
    for (int k = 0; k < KPT; k++)
        acc += v[k].x * v[k].x + v[k].y * v[k].y;
    acc = (t & 0x100) ? -acc : acc;

    #pragma unroll
    for (int o = 16; o > 0; o >>= 1) acc += __shfl_xor_sync(0xffffffffu, acc, o);
    if ((t & 31) == 0) red[t >> 5] = acc;
    __syncthreads();
    if (t < 32) {
        float v2 = (t < NT / 32) ? red[t] : 0.f;
        #pragma unroll
        for (int o = 16; o > 0; o >>= 1) v2 += __shfl_xor_sync(0xffffffffu, v2, o);
        if (t == 0) out[b] = v2;
    }
}

extern "C" void kernel_launch(void* const* d_in, const int* in_sizes, int n_in,
                              void* d_out, int out_size)
{
    const float* x      = (const float*)d_in[0];
    const float* params = (const float*)d_in[1];
    if (n_in >= 2 && in_sizes[0] != 256 && in_sizes[1] == 256) {
        x      = (const float*)d_in[1];
        params = (const float*)d_in[0];
    }
    float* out = (float*)d_out;
    qsim_kernel<<<256, NT>>>(x, params, out);
}

// round 8
// speedup vs baseline: 1.3016x; 1.3016x over previous
#include <cuda_runtime.h>

#define NQ    12
#define DIM   4096
#define NL    4
#define NT    256
#define KPT   16
#define SW(i) ((i) ^ (((i) >> 4) & 0xF))   // bank-conflict swizzle (R5-verified)

struct cplx { float x, y; };

__device__ __forceinline__ cplx cmul(cplx a, cplx b) {
    return { a.x*b.x - a.y*b.y, a.x*b.y + a.y*b.x };
}
__device__ __forceinline__ cplx cadd(cplx a, cplx b) {
    return { a.x + b.x, a.y + b.y };
}
__device__ __forceinline__ void mmul(const cplx* A, const cplx* B, cplx* C) {
    C[0] = cadd(cmul(A[0], B[0]), cmul(A[1], B[2]));
    C[1] = cadd(cmul(A[0], B[1]), cmul(A[1], B[3]));
    C[2] = cadd(cmul(A[2], B[0]), cmul(A[3], B[2]));
    C[3] = cadd(cmul(A[2], B[1]), cmul(A[3], B[3]));
}
// e or conj(e) depending on bit
__device__ __forceinline__ cplx eph(float2 e, int bit) {
    return { e.x, bit ? -e.y : e.y };
}

// real RY rotation on local register bit m of v[16]
__device__ __forceinline__ void apply_ry(float2 v[KPT], float c, float s, int m) {
    #pragma unroll
    for (int h = 0; h < 8; h++) {
        const int k0 = ((h >> m) << (m + 1)) | (h & ((1 << m) - 1));
        const int k1 = k0 | (1 << m);
        const float2 s0 = v[k0];
        const float2 s1 = v[k1];
        v[k0].x = c*s0.x - s*s1.x;
        v[k0].y = c*s0.y - s*s1.y;
        v[k1].x = s*s0.x + c*s1.x;
        v[k1].y = s*s0.y + c*s1.y;
    }
}

__global__ __launch_bounds__(NT, 2)
void qsim_kernel(const float* __restrict__ x,
                 const float* __restrict__ params,
                 float* __restrict__ out)
{
    __shared__ float2 st[DIM];                 // 32 KB state (swizzled)
    __shared__ float2 RYcs[NL][NQ];            // (cos, sin) of RY theta/2
    __shared__ float2 EG[NL][NQ], EA[NL][NQ];  // e^{-i gamma/2}, e^{-i alpha/2}
    __shared__ float2 TA2[NL-1][2][16];        // boundary diag: bits 11..8 (+bit7)
    __shared__ float2 TBt[NL-1][32];           // boundary diag: bits 7..3
    __shared__ float2 TCt[NL-1][16];           // boundary diag: bits 3..0
    __shared__ float  red[NT / 32];

    const int t = threadIdx.x;
    const int b = blockIdx.x;

    // ---- phase 1: 48 fused gates + ZYZ decomposition ----
    if (t < NL * NQ) {
        const int l = t / NQ;
        const int q = t % NQ;
        const float xv = x[b];
        const float x1 = asinf(xv);
        const float x2 = acosf(xv * xv);

        float c, s;
        sincosf(0.5f * x1, &s, &c);
        cplx RY[4]  = { {c,0.f}, {-s,0.f}, {s,0.f}, {c,0.f} };
        sincosf(0.5f * x2, &s, &c);
        cplx RZ[4]  = { {c,-s}, {0.f,0.f}, {0.f,0.f}, {c,s} };

        const float t0 = params[q * (NL * 3) + l * 3 + 0];
        const float t1 = params[q * (NL * 3) + l * 3 + 1];
        const float t2 = params[q * (NL * 3) + l * 3 + 2];

        sincosf(0.5f * t0, &s, &c);
        cplx RX0[4] = { {c,0.f}, {0.f,-s}, {0.f,-s}, {c,0.f} };
        sincosf(0.5f * t1, &s, &c);
        cplx RZ1[4] = { {c,-s}, {0.f,0.f}, {0.f,0.f}, {c,s} };
        sincosf(0.5f * t2, &s, &c);
        cplx RX2[4] = { {c,0.f}, {0.f,-s}, {0.f,-s}, {c,0.f} };

        cplx A[4], B[4];
        mmul(RZ,  RY, A);
        mmul(RX0, A,  B);
        mmul(RZ1, B,  A);
        mmul(RX2, A,  B);   // fused U in SU(2)

        // ZYZ: U = RZ(alpha) RY(theta) RZ(gamma)
        const float cc = sqrtf(B[0].x*B[0].x + B[0].y*B[0].y);
        const float ss = sqrtf(B[2].x*B[2].x + B[2].y*B[2].y);
        RYcs[l][q] = make_float2(cc, ss);
        const float aa = atan2f(-B[0].y, B[0].x);   // (alpha+gamma)/2
        const float bb = atan2f( B[2].y, B[2].x);   // (alpha-gamma)/2
        float sg, cg, sa, ca;
        sincosf(0.5f * (aa - bb), &sg, &cg);
        sincosf(0.5f * (aa + bb), &sa, &ca);
        EG[l][q] = make_float2(cg, -sg);            // e^{-i gamma/2}
        EA[l][q] = make_float2(ca, -sa);            // e^{-i alpha/2}
    }
    __syncthreads();

    // ---- phase 2: fused boundary diagonals D(i) = gamma_{bd+1}(i) * alpha_bd(g(i)),
    //      g(i) = i ^ (i>>1). 80 entries per boundary, 3 boundaries = 240 threads ----
    if (t < (NL - 1) * 80) {
        const int bd = t / 80;          // boundary between layer bd and bd+1
        const int r  = t % 80;
        cplx d = {1.f, 0.f};
        if (r < 32) {
            // TA2[bd][c7][k]: qubits 0..3 on bits 11..8 (k), plus qubit 4 term
            const int c7 = r >> 4;
            const int k  = r & 15;
            const int k3 = (k >> 3) & 1, k2 = (k >> 2) & 1, k1 = (k >> 1) & 1, k0 = k & 1;
            d = cmul(d, eph(EG[bd+1][0], k3));  d = cmul(d, eph(EA[bd][0], k3));
            d = cmul(d, eph(EG[bd+1][1], k2));  d = cmul(d, eph(EA[bd][1], k2 ^ k3));
            d = cmul(d, eph(EG[bd+1][2], k1));  d = cmul(d, eph(EA[bd][2], k1 ^ k2));
            d = cmul(d, eph(EG[bd+1][3], k0));  d = cmul(d, eph(EA[bd][3], k0 ^ k1));
            d = cmul(d, eph(EG[bd+1][4], c7));  d = cmul(d, eph(EA[bd][4], c7 ^ k0));
            TA2[bd][c7][k] = make_float2(d.x, d.y);
        } else if (r < 64) {
            // TBt[bd][u]: qubits 5..8; u_j = bit (j+3) of i
            const int u = r - 32;
            const int u4 = (u >> 4) & 1, u3 = (u >> 3) & 1, u2 = (u >> 2) & 1,
                      u1 = (u >> 1) & 1, u0 = u & 1;
            d = cmul(d, eph(EG[bd+1][5], u3));  d = cmul(d, eph(EA[bd][5], u3 ^ u4));
            d = cmul(d, eph(EG[bd+1][6], u2));  d = cmul(d, eph(EA[bd][6], u2 ^ u3));
            d = cmul(d, eph(EG[bd+1][7], u1));  d = cmul(d, eph(EA[bd][7], u1 ^ u2));
            d = cmul(d, eph(EG[bd+1][8], u0));  d = cmul(d, eph(EA[bd][8], u0 ^ u1));
            TBt[bd][u] = make_float2(d.x, d.y);
        } else {
            // TCt[bd][w]: qubits 9..11; w_j = bit j of i
            const int w = r - 64;
            const int w3 = (w >> 3) & 1, w2 = (w >> 2) & 1, w1 = (w >> 1) & 1, w0 = w & 1;
            d = cmul(d, eph(EG[bd+1][9],  w2)); d = cmul(d, eph(EA[bd][9],  w2 ^ w3));
            d = cmul(d, eph(EG[bd+1][10], w1)); d = cmul(d, eph(EA[bd][10], w1 ^ w2));
            d = cmul(d, eph(EG[bd+1][11], w0)); d = cmul(d, eph(EA[bd][11], w0 ^ w1));
            TCt[bd][w] = make_float2(d.x, d.y);
        }
    }
    __syncthreads();

    float2 v[KPT];

    // RY-only pass: 4 qubits on register bits 3..0, qubit 4P+3-m on bit m
    #define RY_PASS(L, P)                                                     \
        {                                                                     \
            _Pragma("unroll")                                                 \
            for (int m = 0; m < 4; m++) {                                     \
                const float2 cs = RYcs[L][4*(P) + 3 - m];                     \
                apply_ry(v, cs.x, cs.y, m);                                   \
            }                                                                 \
        }

    // ======== layer 0: pure real Kronecker column (gamma_0 = global phase) ====
    {
        float w = 1.f;
        #pragma unroll
        for (int q = 0; q < 8; q++) {
            const float2 cs = RYcs[0][q];
            w *= ((t >> (7 - q)) & 1) ? cs.y : cs.x;
        }
        const float2 c8 = RYcs[0][8], c9 = RYcs[0][9], c10 = RYcs[0][10], c11 = RYcs[0][11];
        const int base = t << 4;
        #pragma unroll
        for (int k = 0; k < KPT; k++) {
            const float col = ((k & 8) ? c8.y  : c8.x)  *
                              ((k & 4) ? c9.y  : c9.x)  *
                              ((k & 2) ? c10.y : c10.x) *
                              ((k & 1) ? c11.y : c11.x);
            st[SW(base | k)] = make_float2(w * col, 0.f);
        }
        __syncthreads();
    }

    // ======== layers 1..3 ========
    for (int l = 1; l < NL; l++) {
        const int bd = l - 1;

        // pass 0 (bits 11..8, qubits 0..3): perm-gather + fused boundary diagonal
        {
            const float2 tb = TBt[bd][(t >> 3) & 31];
            const float2 tc = TCt[bd][t & 15];
            const cplx  sc = cmul(cplx{tb.x, tb.y}, cplx{tc.x, tc.y});
            const float2* ta = &TA2[bd][(t >> 7) & 1][0];
            #pragma unroll
            for (int k = 0; k < KPT; k++) {
                const int i = (k << 8) | t;
                const int j = i ^ (i >> 1);
                const float2 s0 = st[SW(j)];
                const float2 a  = ta[k];
                const cplx  d  = cmul(sc, cplx{a.x, a.y});
                v[k].x = d.x*s0.x - d.y*s0.y;
                v[k].y = d.x*s0.y + d.y*s0.x;
            }
            __syncthreads();
            RY_PASS(l, 0)
            #pragma unroll
            for (int k = 0; k < KPT; k++) st[SW((k << 8) | t)] = v[k];
            __syncthreads();
        }

        // pass 1 (bits 7..4, qubits 4..7)
        {
            const int base = ((t & 0xF0) << 4) | (t & 0x0F);
            #pragma unroll
            for (int k = 0; k < KPT; k++) v[k] = st[SW(base | (k << 4))];
            RY_PASS(l, 1)
            #pragma unroll
            for (int k = 0; k < KPT; k++) st[SW(base | (k << 4))] = v[k];
            __syncthreads();
        }

        // pass 2 (bits 3..0, qubits 8..11)
        {
            const int base = t << 4;
            #pragma unroll
            for (int k = 0; k < KPT; k++) v[k] = st[SW(base | k)];
            RY_PASS(l, 2)
            if (l < NL - 1) {
                #pragma unroll
                for (int k = 0; k < KPT; k++) st[SW(base | k)] = v[k];
                __syncthreads();
            }
            // last layer: stay in registers. Final CNOT perm preserves bit 11,
            // and the dropped alpha_3 diagonal is modulus-preserving.
        }
    }

    // ---- <Z_0>: sign = bit 11 of i = (t<<4)|k -> bit 7 of t ----
    float acc = 0.f;
    #pragma unroll
    for (int k = 0; k < KPT; k++)
        acc += v[k].x * v[k].x + v[k].y * v[k].y;
    acc = (t & 0x80) ? -acc : acc;

    #pragma unroll
    for (int o = 16; o > 0; o >>= 1) acc += __shfl_xor_sync(0xffffffffu, acc, o);
    if ((t & 31) == 0) red[t >> 5] = acc;
    __syncthreads();
    if (t < 32) {
        float v2 = (t < NT / 32) ? red[t] : 0.f;
        #pragma unroll
        for (int o = 4; o > 0; o >>= 1) v2 += __shfl_xor_sync(0xffffffffu, v2, o);
        if (t == 0) out[b] = v2;
    }
}

extern "C" void kernel_launch(void* const* d_in, const int* in_sizes, int n_in,
                              void* d_out, int out_size)
{
    const float* x      = (const float*)d_in[0];
    const float* params = (const float*)d_in[1];
    if (n_in >= 2 && in_sizes[0] != 256 && in_sizes[1] == 256) {
        x      = (const float*)d_in[1];
        params = (const float*)d_in[0];
    }
    float* out = (float*)d_out;
    qsim_kernel<<<256, NT>>>(x, params, out);
}